// round 16
// baseline (speedup 1.0000x reference)
#include <cuda_runtime.h>

#define SEQ 2048
#define BB  64
#define IND 512
#define HH  512
#define NCTA 128
#define NTHR 256

typedef unsigned long long ull;

// ---------------- global scratch (static device memory: allowed) ----------------
// gx layout: [t][group(8)][cta(16)] blocks of 8 rows x 96 cols
// (cols 0-31 z-pre, 32-63 r-pre, 64-95 cand-pre), biases folded. Block = 768 floats.
__device__ float g_gx[(size_t)SEQ * 8 * 16 * 768];
__device__ float g_h[BB * HH];        // current hidden state
__device__ float g_rh[BB * HH];       // r * h_prev
__device__ unsigned g_ctr[32 * 32];   // 8 groups x {alphaA, alphaB, betaA, betaB}, padded

// ---------------- helpers ----------------
__device__ __forceinline__ ull ffma2(ull a, ull b, ull c) {
    ull d;
    asm("fma.rn.f32x2 %0, %1, %2, %3;" : "=l"(d) : "l"(a), "l"(b), "l"(c));
    return d;
}
__device__ __forceinline__ float ull_sum(ull v) {
    return __uint_as_float((unsigned)(v & 0xffffffffULL)) +
           __uint_as_float((unsigned)(v >> 32));
}
__device__ __forceinline__ float sigmoidf_(float x) {
    return 1.0f / (1.0f + __expf(-x));
}
__device__ __forceinline__ float tanhf_(float x) {
    return 1.0f - 2.0f / (__expf(2.0f * x) + 1.0f);
}
__device__ __forceinline__ void bar_arrive(unsigned* ctr) {
    __syncthreads();
    if (threadIdx.x == 0)
        asm volatile("red.release.gpu.global.add.u32 [%0], %1;"
                     :: "l"(ctr), "r"(1u) : "memory");
}
__device__ __forceinline__ void bar_wait(unsigned* ctr, unsigned goal) {
    if (threadIdx.x == 0) {
        unsigned v;
        do {
            asm volatile("ld.acquire.gpu.u32 %0, [%1];" : "=r"(v) : "l"(ctr) : "memory");
        } while (v < goal);
    }
    __syncthreads();
}

// ---------------- precompute: gx = x @ [Wg_x | Wc_x] + [bg | bc], remapped ----
__global__ void __launch_bounds__(NTHR) precompute_kernel(
    const float* __restrict__ x, const float* __restrict__ Wg,
    const float* __restrict__ bg, const float* __restrict__ Wc,
    const float* __restrict__ bc, const float* __restrict__ h0)
{
    __shared__ float2 as2[8 * 128];
    __shared__ float2 bs2[8 * 64];

    const int tid = threadIdx.x;

    if (blockIdx.x == 0 && blockIdx.y == 0) {
        for (int i = tid; i < BB * HH; i += NTHR) g_h[i] = h0[i];
        if (tid < 32) g_ctr[tid * 32] = 0u;
    }

    const int bx = blockIdx.x;          // 0..11 (8 Wg tiles, 4 Wc tiles)
    const int m0 = blockIdx.y * 128;

    const float* Wp; const float* bias; int ldw, n0;
    if (bx < 8) { Wp = Wg; bias = bg; ldw = 1024; n0 = bx * 128; }
    else        { Wp = Wc; bias = bc; ldw = 512;  n0 = (bx - 8) * 128; }

    const int tx = tid & 15, ty = tid >> 4;
    const int arow = tid >> 1, acol = (tid & 1) * 4;
    const int bkrow = tid >> 5, bcol2 = (tid & 31) * 2;

    const float* aptr = x + (size_t)(m0 + arow) * IND + acol;
    const float* bptr = Wp + (size_t)bkrow * ldw + n0 + bcol2 * 2;

    float4 areg = *(const float4*)aptr;
    float4 breg = *(const float4*)bptr;

    ull acc[8][4];
#pragma unroll
    for (int i = 0; i < 8; ++i)
#pragma unroll
        for (int j = 0; j < 4; ++j) acc[i][j] = 0ULL;

    for (int kt = 0; kt < IND / 8; ++kt) {
        as2[(acol + 0) * 128 + arow] = make_float2(areg.x, areg.x);
        as2[(acol + 1) * 128 + arow] = make_float2(areg.y, areg.y);
        as2[(acol + 2) * 128 + arow] = make_float2(areg.z, areg.z);
        as2[(acol + 3) * 128 + arow] = make_float2(areg.w, areg.w);
        *(float4*)&bs2[bkrow * 64 + bcol2] = breg;
        __syncthreads();
        if (kt + 1 < IND / 8) {
            areg = *(const float4*)(aptr + (kt + 1) * 8);
            breg = *(const float4*)(bptr + (size_t)(kt + 1) * 8 * ldw);
        }
#pragma unroll
        for (int k = 0; k < 8; ++k) {
            ulonglong2 a01 = *(const ulonglong2*)&as2[k * 128 + ty * 8];
            ulonglong2 a23 = *(const ulonglong2*)&as2[k * 128 + ty * 8 + 2];
            ulonglong2 a45 = *(const ulonglong2*)&as2[k * 128 + ty * 8 + 4];
            ulonglong2 a67 = *(const ulonglong2*)&as2[k * 128 + ty * 8 + 6];
            ulonglong2 b01 = *(const ulonglong2*)&bs2[k * 64 + tx * 4];
            ulonglong2 b23 = *(const ulonglong2*)&bs2[k * 64 + tx * 4 + 2];
            ull av[8] = {a01.x, a01.y, a23.x, a23.y, a45.x, a45.y, a67.x, a67.y};
            ull bv[4] = {b01.x, b01.y, b23.x, b23.y};
#pragma unroll
            for (int i = 0; i < 8; ++i)
#pragma unroll
                for (int j = 0; j < 4; ++j)
                    acc[i][j] = ffma2(av[i], bv[j], acc[i][j]);
        }
        __syncthreads();
    }

    float bvl[8];
#pragma unroll
    for (int j = 0; j < 8; ++j) bvl[j] = bias[n0 + tx * 8 + j];

    // Destination remap: (bx, tx) -> (cta, slot)
    int cta, slot;
    if (bx < 8) {
        int gcol = bx * 128 + tx * 8;
        if (gcol < 512) { cta = gcol >> 5; slot = gcol & 31; }
        else { int rc = gcol - 512; cta = rc >> 5; slot = 32 + (rc & 31); }
    } else {
        int ccol = (bx - 8) * 128 + tx * 8;
        cta = ccol >> 5; slot = 64 + (ccol & 31);
    }

#pragma unroll
    for (int i = 0; i < 8; ++i) {
        int m = m0 + ty * 8 + i;
        int t = m >> 6, b = m & 63, g = b >> 3, r = b & 7;
        float* op = g_gx + (((size_t)t * 8 + g) * 16 + cta) * 768 + r * 96 + slot;
        float2 c0, c1, c2, c3;
        c0.x = __uint_as_float((unsigned)acc[i][0]); c0.y = __uint_as_float((unsigned)(acc[i][0] >> 32));
        c1.x = __uint_as_float((unsigned)acc[i][1]); c1.y = __uint_as_float((unsigned)(acc[i][1] >> 32));
        c2.x = __uint_as_float((unsigned)acc[i][2]); c2.y = __uint_as_float((unsigned)(acc[i][2] >> 32));
        c3.x = __uint_as_float((unsigned)acc[i][3]); c3.y = __uint_as_float((unsigned)(acc[i][3] >> 32));
        *(float4*)(op)     = make_float4(c0.x + bvl[0], c0.y + bvl[1],
                                         c1.x + bvl[2], c1.y + bvl[3]);
        *(float4*)(op + 4) = make_float4(c2.x + bvl[4], c2.y + bvl[5],
                                         c3.x + bvl[6], c3.y + bvl[7]);
    }
}

// ---------------- scan building blocks (4-row chain GEMMs) ----------------
// GEMM: 4 rows x 32 cols x 512 k. 8 warps; warp ks owns k-slice [ks*64,+64).
// Lane: rg2 = ln>>3 (row 0..3), cg2 = ln&7; thread tile 1 row x 4 cols.
// Partials: P[(ks*4 + j)*32 + ln], 8*4*32 = 1024 floats.
__device__ __forceinline__ void gemm4(const float* __restrict__ hb,
                                      const float* __restrict__ wb,
                                      float* __restrict__ Pout,
                                      int ks, int ln, int rg2, int cg2)
{
    ull acc[4];
#pragma unroll
    for (int j = 0; j < 4; ++j) acc[j] = 0ULL;

    const int kc0 = ks * 16;
#pragma unroll 4
    for (int tt = 0; tt < 16; ++tt) {
        int kc = kc0 + tt;
        ulonglong2 hv = *(const ulonglong2*)&hb[rg2 * 512 + ((kc ^ rg2) << 2)];
        ulonglong2 wv[4];
#pragma unroll
        for (int j = 0; j < 4; ++j) {
            int c = cg2 * 4 + j;
            wv[j] = *(const ulonglong2*)&wb[c * 512 + ((kc ^ cg2) << 2)];
        }
#pragma unroll
        for (int j = 0; j < 4; ++j) {
            acc[j] = ffma2(hv.x, wv[j].x, acc[j]);
            acc[j] = ffma2(hv.y, wv[j].y, acc[j]);
        }
    }
#pragma unroll
    for (int j = 0; j < 4; ++j)
        Pout[(ks * 4 + j) * 32 + ln] = ull_sum(acc[j]);
}

// Per-warp staging: warp ks loads its k-slice for 4 rows (4 x 64 k = 1 KB).
__device__ __forceinline__ void stage4(float* __restrict__ hst,
                                       const float* __restrict__ src,
                                       int rbase, int ks, int ln)
{
#pragma unroll
    for (int i = 0; i < 2; ++i) {
        int idx = i * 32 + ln;                    // 0..63
        int row = idx >> 4;                       // 0..3
        int kc  = ks * 16 + (idx & 15);
        float4 v = __ldcg((const float4*)(src + (size_t)(rbase + row) * HH + kc * 4));
        *(float4*)&hst[row * 512 + ((kc ^ row) << 2)] = v;
    }
}

// owner reduce: sum 8 warps' partials for value v (=ks of owner), lane ln.
__device__ __forceinline__ float reduceP(const float* __restrict__ P, int v, int ln) {
    float s = 0.f;
#pragma unroll
    for (int q = 0; q < 8; ++q) s += P[(q * 4 + v) * 32 + ln];
    return s;
}

// ---------------- persistent scan kernel ----------------
// 128 CTAs x 256 thr, 1/SM. Group g = bid>>4 owns rows [g*8,+8):
// chain alpha = rows [g*8, +4), chain beta = rows [g*8+4, +4). Chains are
// independent GRU recurrences, software-pipelined half a step apart so every
// barrier wait is covered by the other chain's GEMM work.
// smem (floats): wg 32x512 z | 32x512 r | wc 32x512 | hstA 2048 | hstB 2048
//               | PA 1024 | PB 1024  = 55296 floats = 221184 B
#define SM_WG   0
#define SM_WC   32768
#define SM_HSTA 49152
#define SM_HSTB 51200
#define SM_PA   53248
#define SM_PB   54272
#define SMEM_FLOATS 55296
#define SMEM_BYTES (SMEM_FLOATS * 4)

__global__ void __launch_bounds__(NTHR, 1) scan_kernel(
    const float* __restrict__ Wg, const float* __restrict__ Wc,
    float* __restrict__ out, int write_outputs, int write_hlast)
{
    extern __shared__ float sm[];
    float* wg   = sm + SM_WG;          // cols 0-31 = z, 32-63 = r
    float* wc   = sm + SM_WC;
    float* hstA = sm + SM_HSTA;
    float* hstB = sm + SM_HSTB;
    float* PA   = sm + SM_PA;
    float* PB   = sm + SM_PB;
    float* wgr  = wg + 32 * 512;

    const int tid = threadIdx.x;
    const int g   = blockIdx.x >> 4;
    const int cid = blockIdx.x & 15;
    const int r0  = g * 8;             // alpha rows r0..r0+3, beta rows r0+4..r0+7
    const int c32 = cid * 32;

    // ---- load recurrent weight slabs once (swizzled, k-contiguous per col) ----
    for (int idx = tid; idx < 64 * 512; idx += NTHR) {
        int k = idx >> 6, c = idx & 63;
        int gc = (c < 32) ? (c32 + c) : (512 + c32 + (c - 32));
        float v = Wg[(size_t)(512 + k) * 1024 + gc];
        wg[c * 512 + (((k >> 2) ^ ((c >> 2) & 7)) << 2) + (k & 3)] = v;
    }
    for (int idx = tid; idx < 32 * 512; idx += NTHR) {
        int k = idx >> 5, c = idx & 31;
        float v = Wc[(size_t)(512 + k) * 512 + c32 + c];
        wc[c * 512 + (((k >> 2) ^ ((c >> 2) & 7)) << 2) + (k & 3)] = v;
    }
    __syncthreads();

    const int ks  = tid >> 5;          // 0..7 (k-slice warp)
    const int ln  = tid & 31;
    const int rg2 = ln >> 3, cg2 = ln & 7;

    // owner threads: warps 0-3 (tid<128); owner value v = ks (0..3)
    const bool owner = (tid < 128);
    const int v2   = ks & 3;
    const int row2 = rg2;                         // 0..3 within chain
    const int col2 = cg2 * 4 + v2;
    const int jj2  = c32 + col2;
    const int bA   = r0 + row2;                   // alpha batch row
    const int bB   = r0 + 4 + row2;               // beta batch row

    unsigned* ctrAA = g_ctr + (g * 4 + 0) * 32;   // alpha phase1 (rh ready)
    unsigned* ctrAB = g_ctr + (g * 4 + 1) * 32;   // alpha phase2 (h ready)
    unsigned* ctrBA = g_ctr + (g * 4 + 2) * 32;   // beta  phase1
    unsigned* ctrBB = g_ctr + (g * 4 + 3) * 32;   // beta  phase2

    float hprevA = owner ? __ldcg(g_h + (size_t)bA * HH + jj2) : 0.f;
    float hprevB = owner ? __ldcg(g_h + (size_t)bB * HH + jj2) : 0.f;

    // gx prefetch state (per chain): z, r, cand pre-activations
    const float* gbase = g_gx + ((size_t)g * 16 + cid) * 768;
    const size_t gstep = (size_t)8 * 16 * 768;
    float gxzA = 0.f, gxrA = 0.f, gxcA = 0.f;
    float gxzB = 0.f, gxrB = 0.f, gxcB = 0.f;
    if (owner) {
        const float* gb = gbase;                   // t = 0
        gxzA = __ldcg(gb + row2 * 96 + col2);
        gxrA = __ldcg(gb + row2 * 96 + 32 + col2);
        gxcA = __ldcg(gb + row2 * 96 + 64 + col2);
        gxzB = __ldcg(gb + (4 + row2) * 96 + col2);
        gxrB = __ldcg(gb + (4 + row2) * 96 + 32 + col2);
        gxcB = __ldcg(gb + (4 + row2) * 96 + 64 + col2);
    }

    // ---- preamble: alpha r-phase for t = 0 ----
    stage4(hstA, g_h, r0, ks, ln);
    __syncwarp();
    gemm4(hstA, wgr, PA, ks, ln, rg2, cg2);
    __syncthreads();
    if (owner) {
        float r = sigmoidf_(reduceP(PA, v2, ln) + gxrA);
        __stcg(g_rh + (size_t)bA * HH + jj2, r * hprevA);
    }
    bar_arrive(ctrAA);

    float hnA = 0.f, hnB = 0.f;

    for (int t = 0; t < SEQ; ++t) {
        const unsigned goal = (unsigned)(t + 1) * 16u;

        // ---- 1: beta r-phase (t) ----
        stage4(hstB, g_h, r0 + 4, ks, ln);
        __syncwarp();
        gemm4(hstB, wgr, PB, ks, ln, rg2, cg2);
        __syncthreads();
        if (owner) {
            float r = sigmoidf_(reduceP(PB, v2, ln) + gxrB);
            __stcg(g_rh + (size_t)bB * HH + jj2, r * hprevB);
        }
        bar_arrive(ctrBA);

        // ---- 2: alpha z (t) — hides wait on alpha A ----
        gemm4(hstA, wg, PA, ks, ln, rg2, cg2);
        __syncthreads();
        float zA = 0.f;
        if (owner) zA = sigmoidf_(reduceP(PA, v2, ln) + gxzA);

        // ---- 3: wait alpha rh exchange ----
        bar_wait(ctrAA, goal);

        // ---- 4: alpha cand (t) + h update; prefetch alpha gx(t+1) ----
        if (owner && t + 1 < SEQ) {
            const float* gb = gbase + (size_t)(t + 1) * gstep;
            gxzA = __ldcg(gb + row2 * 96 + col2);
            gxrA = __ldcg(gb + row2 * 96 + 32 + col2);
        }
        stage4(hstA, g_rh, r0, ks, ln);
        __syncwarp();
        gemm4(hstA, wc, PA, ks, ln, rg2, cg2);
        __syncthreads();
        if (owner) {
            float cand = tanhf_(reduceP(PA, v2, ln) + gxcA);
            hnA = fmaf(zA, cand - hprevA, hprevA);
            __stcg(g_h + (size_t)bA * HH + jj2, hnA);
            if (t + 1 < SEQ)
                gxcA = __ldcg(gbase + (size_t)(t + 1) * gstep + row2 * 96 + 64 + col2);
        }
        bar_arrive(ctrAB);

        // ---- 5: beta z (t) — hides wait on beta A ----
        gemm4(hstB, wg, PB, ks, ln, rg2, cg2);
        __syncthreads();
        float zB = 0.f;
        if (owner) zB = sigmoidf_(reduceP(PB, v2, ln) + gxzB);

        // ---- 6: wait beta rh exchange ----
        bar_wait(ctrBA, goal);

        // ---- 7: beta cand (t) + h update; prefetch beta gx(t+1) ----
        if (owner && t + 1 < SEQ) {
            const float* gb = gbase + (size_t)(t + 1) * gstep;
            gxzB = __ldcg(gb + (4 + row2) * 96 + col2);
            gxrB = __ldcg(gb + (4 + row2) * 96 + 32 + col2);
        }
        stage4(hstB, g_rh, r0 + 4, ks, ln);
        __syncwarp();
        gemm4(hstB, wc, PB, ks, ln, rg2, cg2);
        __syncthreads();
        if (owner) {
            float cand = tanhf_(reduceP(PB, v2, ln) + gxcB);
            hnB = fmaf(zB, cand - hprevB, hprevB);
            __stcg(g_h + (size_t)bB * HH + jj2, hnB);
            if (t + 1 < SEQ)
                gxcB = __ldcg(gbase + (size_t)(t + 1) * gstep + (4 + row2) * 96 + 64 + col2);
        }
        bar_arrive(ctrBB);

        // ---- 8: alpha out store (t); then alpha r-phase for t+1 ----
        if (owner) {
            if (write_outputs)
                __stcs(out + ((size_t)t * BB + bA) * HH + jj2, hnA);
            if (write_hlast && t == SEQ - 1) {
                size_t off = write_outputs ? (size_t)SEQ * BB * HH : 0;
                out[off + (size_t)bA * HH + jj2] = hnA;
            }
            hprevA = hnA;
        }
        if (t + 1 < SEQ) {
            bar_wait(ctrAB, goal);                 // h(t+1) exchange done
            stage4(hstA, g_h, r0, ks, ln);
            __syncwarp();
            gemm4(hstA, wgr, PA, ks, ln, rg2, cg2);
            __syncthreads();
            if (owner) {
                float r = sigmoidf_(reduceP(PA, v2, ln) + gxrA);
                __stcg(g_rh + (size_t)bA * HH + jj2, r * hprevA);
            }
            bar_arrive(ctrAA);
        }

        // ---- 9: beta out store (t) ----
        if (owner) {
            if (write_outputs)
                __stcs(out + ((size_t)t * BB + bB) * HH + jj2, hnB);
            if (write_hlast && t == SEQ - 1) {
                size_t off = write_outputs ? (size_t)SEQ * BB * HH : 0;
                out[off + (size_t)bB * HH + jj2] = hnB;
            }
            hprevB = hnB;
        }
        if (t + 1 < SEQ)
            bar_wait(ctrBB, goal);                 // covered by alpha r-phase above
    }
}

// ---------------- launch ----------------
extern "C" void kernel_launch(void* const* d_in, const int* in_sizes, int n_in,
                              void* d_out, int out_size) {
    const float* x  = (const float*)d_in[0];
    const float* h0 = (const float*)d_in[1];
    const float* Wg = (const float*)d_in[2];
    const float* bg = (const float*)d_in[3];
    const float* Wc = (const float*)d_in[4];
    const float* bc = (const float*)d_in[5];
    float* out = (float*)d_out;

    cudaFuncSetAttribute(scan_kernel, cudaFuncAttributeMaxDynamicSharedMemorySize,
                         SMEM_BYTES);

    long long full = (long long)SEQ * BB * HH;
    int write_outputs = (out_size >= full) ? 1 : 0;
    long long hlast_off = write_outputs ? full : 0;
    int write_hlast = (out_size >= hlast_off + BB * HH) ? 1 : 0;

    dim3 pgrid(12, 1024);
    precompute_kernel<<<pgrid, NTHR>>>(x, Wg, bg, Wc, bc, h0);
    scan_kernel<<<NCTA, NTHR, SMEM_BYTES>>>(Wg, Wc, out, write_outputs, write_hlast);
}

// round 17
// speedup vs baseline: 2.4212x; 2.4212x over previous
#include <cuda_runtime.h>

#define SEQ 2048
#define BB  64
#define IND 512
#define HH  512
#define NCTA 128
#define NTHR 256

typedef unsigned long long ull;

// ---------------- global scratch (static device memory: allowed) ----------------
// gx layout: [t][group(8)][cta(16)] blocks of 8 rows x 96 cols
// (cols 0-31 z-pre, 32-63 r-pre, 64-95 cand-pre), biases folded. Block = 768 floats.
__device__ float g_gx[(size_t)SEQ * 8 * 16 * 768];
__device__ float g_h[BB * HH];        // current hidden state
__device__ float g_rh[BB * HH];       // r * h_prev
__device__ unsigned g_ctr[16 * 32];   // 16 barrier counters, padded to 128B lines

// ---------------- helpers ----------------
__device__ __forceinline__ ull ffma2(ull a, ull b, ull c) {
    ull d;
    asm("fma.rn.f32x2 %0, %1, %2, %3;" : "=l"(d) : "l"(a), "l"(b), "l"(c));
    return d;
}
__device__ __forceinline__ float ull_sum(ull v) {
    return __uint_as_float((unsigned)(v & 0xffffffffULL)) +
           __uint_as_float((unsigned)(v >> 32));
}
__device__ __forceinline__ float sigmoidf_(float x) {
    return 1.0f / (1.0f + __expf(-x));
}
__device__ __forceinline__ float tanhf_(float x) {
    return 1.0f - 2.0f / (__expf(2.0f * x) + 1.0f);
}
__device__ __forceinline__ void bar_arrive(unsigned* ctr) {
    __syncthreads();
    if (threadIdx.x == 0)
        asm volatile("red.release.gpu.global.add.u32 [%0], %1;"
                     :: "l"(ctr), "r"(1u) : "memory");
}
__device__ __forceinline__ void bar_wait(unsigned* ctr, unsigned goal) {
    if (threadIdx.x == 0) {
        unsigned v;
        do {
            asm volatile("ld.acquire.gpu.u32 %0, [%1];" : "=r"(v) : "l"(ctr) : "memory");
        } while (v < goal);
    }
    __syncthreads();
}

// ---------------- precompute: gx = x @ [Wg_x | Wc_x] + [bg | bc], remapped ----
__global__ void __launch_bounds__(NTHR) precompute_kernel(
    const float* __restrict__ x, const float* __restrict__ Wg,
    const float* __restrict__ bg, const float* __restrict__ Wc,
    const float* __restrict__ bc, const float* __restrict__ h0)
{
    __shared__ float2 as2[8 * 128];
    __shared__ float2 bs2[8 * 64];

    const int tid = threadIdx.x;

    if (blockIdx.x == 0 && blockIdx.y == 0) {
        for (int i = tid; i < BB * HH; i += NTHR) g_h[i] = h0[i];
        if (tid < 16) g_ctr[tid * 32] = 0u;
    }

    const int bx = blockIdx.x;          // 0..11 (8 Wg tiles, 4 Wc tiles)
    const int m0 = blockIdx.y * 128;

    const float* Wp; const float* bias; int ldw, n0;
    if (bx < 8) { Wp = Wg; bias = bg; ldw = 1024; n0 = bx * 128; }
    else        { Wp = Wc; bias = bc; ldw = 512;  n0 = (bx - 8) * 128; }

    const int tx = tid & 15, ty = tid >> 4;
    const int arow = tid >> 1, acol = (tid & 1) * 4;
    const int bkrow = tid >> 5, bcol2 = (tid & 31) * 2;

    const float* aptr = x + (size_t)(m0 + arow) * IND + acol;
    const float* bptr = Wp + (size_t)bkrow * ldw + n0 + bcol2 * 2;

    float4 areg = *(const float4*)aptr;
    float4 breg = *(const float4*)bptr;

    ull acc[8][4];
#pragma unroll
    for (int i = 0; i < 8; ++i)
#pragma unroll
        for (int j = 0; j < 4; ++j) acc[i][j] = 0ULL;

    for (int kt = 0; kt < IND / 8; ++kt) {
        as2[(acol + 0) * 128 + arow] = make_float2(areg.x, areg.x);
        as2[(acol + 1) * 128 + arow] = make_float2(areg.y, areg.y);
        as2[(acol + 2) * 128 + arow] = make_float2(areg.z, areg.z);
        as2[(acol + 3) * 128 + arow] = make_float2(areg.w, areg.w);
        *(float4*)&bs2[bkrow * 64 + bcol2] = breg;
        __syncthreads();
        if (kt + 1 < IND / 8) {
            areg = *(const float4*)(aptr + (kt + 1) * 8);
            breg = *(const float4*)(bptr + (size_t)(kt + 1) * 8 * ldw);
        }
#pragma unroll
        for (int k = 0; k < 8; ++k) {
            ulonglong2 a01 = *(const ulonglong2*)&as2[k * 128 + ty * 8];
            ulonglong2 a23 = *(const ulonglong2*)&as2[k * 128 + ty * 8 + 2];
            ulonglong2 a45 = *(const ulonglong2*)&as2[k * 128 + ty * 8 + 4];
            ulonglong2 a67 = *(const ulonglong2*)&as2[k * 128 + ty * 8 + 6];
            ulonglong2 b01 = *(const ulonglong2*)&bs2[k * 64 + tx * 4];
            ulonglong2 b23 = *(const ulonglong2*)&bs2[k * 64 + tx * 4 + 2];
            ull av[8] = {a01.x, a01.y, a23.x, a23.y, a45.x, a45.y, a67.x, a67.y};
            ull bv[4] = {b01.x, b01.y, b23.x, b23.y};
#pragma unroll
            for (int i = 0; i < 8; ++i)
#pragma unroll
                for (int j = 0; j < 4; ++j)
                    acc[i][j] = ffma2(av[i], bv[j], acc[i][j]);
        }
        __syncthreads();
    }

    float bvl[8];
#pragma unroll
    for (int j = 0; j < 8; ++j) bvl[j] = bias[n0 + tx * 8 + j];

    // Destination remap: (bx, tx) -> (cta, slot)
    int cta, slot;
    if (bx < 8) {
        int gcol = bx * 128 + tx * 8;
        if (gcol < 512) { cta = gcol >> 5; slot = gcol & 31; }
        else { int rc = gcol - 512; cta = rc >> 5; slot = 32 + (rc & 31); }
    } else {
        int ccol = (bx - 8) * 128 + tx * 8;
        cta = ccol >> 5; slot = 64 + (ccol & 31);
    }

#pragma unroll
    for (int i = 0; i < 8; ++i) {
        int m = m0 + ty * 8 + i;
        int t = m >> 6, b = m & 63, g = b >> 3, r = b & 7;
        float* op = g_gx + (((size_t)t * 8 + g) * 16 + cta) * 768 + r * 96 + slot;
        float2 c0, c1, c2, c3;
        c0.x = __uint_as_float((unsigned)acc[i][0]); c0.y = __uint_as_float((unsigned)(acc[i][0] >> 32));
        c1.x = __uint_as_float((unsigned)acc[i][1]); c1.y = __uint_as_float((unsigned)(acc[i][1] >> 32));
        c2.x = __uint_as_float((unsigned)acc[i][2]); c2.y = __uint_as_float((unsigned)(acc[i][2] >> 32));
        c3.x = __uint_as_float((unsigned)acc[i][3]); c3.y = __uint_as_float((unsigned)(acc[i][3] >> 32));
        *(float4*)(op)     = make_float4(c0.x + bvl[0], c0.y + bvl[1],
                                         c1.x + bvl[2], c1.y + bvl[3]);
        *(float4*)(op + 4) = make_float4(c2.x + bvl[4], c2.y + bvl[5],
                                         c3.x + bvl[6], c3.y + bvl[7]);
    }
}

// ---------------- scan kernel building blocks ----------------
// hst layout: row stride 516 floats (no swizzle; 516*4B = 2064B keeps rows on
// distinct bank groups for stride-2 row reads). Warp ks owns float4-chunks
// kc in [ks*16, ks*16+16) -> k [ks*64,+64). hst slices are warp-private for
// both staging writes and GEMM reads.
#define HSTRIDE 516

// GEMM: 8 rows x 32 cols x 512 k. Lane = (rg2 = ln>>3, cg2 = ln&7); thread
// tile 2 rows x 4 cols, 16 k-chunks. Partials -> Pout[(ks*8 + i*4 + j)*32 + ln].
__device__ __forceinline__ void gemm8(const float* __restrict__ hb,
                                      const float* __restrict__ wb,
                                      float* __restrict__ Pout,
                                      int ks, int ln, int rg2, int cg2)
{
    ull acc[2][4];
#pragma unroll
    for (int i = 0; i < 2; ++i)
#pragma unroll
        for (int j = 0; j < 4; ++j) acc[i][j] = 0ULL;

    const int kc0 = ks * 16;
    const ulonglong2* hp0 = (const ulonglong2*)&hb[(rg2 * 2 + 0) * HSTRIDE + kc0 * 4];
    const ulonglong2* hp1 = (const ulonglong2*)&hb[(rg2 * 2 + 1) * HSTRIDE + kc0 * 4];

#pragma unroll
    for (int tt = 0; tt < 16; ++tt) {
        int kc = kc0 + tt;
        ulonglong2 hv0 = hp0[tt];
        ulonglong2 hv1 = hp1[tt];
        unsigned xo = (unsigned)((kc ^ cg2) << 2);
        ulonglong2 wv[4];
#pragma unroll
        for (int j = 0; j < 4; ++j)
            wv[j] = *(const ulonglong2*)&wb[(cg2 * 4 + j) * 512 + xo];
#pragma unroll
        for (int j = 0; j < 4; ++j) {
            acc[0][j] = ffma2(hv0.x, wv[j].x, acc[0][j]);
            acc[0][j] = ffma2(hv0.y, wv[j].y, acc[0][j]);
            acc[1][j] = ffma2(hv1.x, wv[j].x, acc[1][j]);
            acc[1][j] = ffma2(hv1.y, wv[j].y, acc[1][j]);
        }
    }
#pragma unroll
    for (int i = 0; i < 2; ++i)
#pragma unroll
        for (int j = 0; j < 4; ++j)
            Pout[(ks * 8 + i * 4 + j) * 32 + ln] = ull_sum(acc[i][j]);
}

// Per-warp staging, split into LDG (issue early) and STS (commit late).
__device__ __forceinline__ void stage_ldg(float4* reg,
                                          const float* __restrict__ src,
                                          int r0, int ks, int ln)
{
#pragma unroll
    for (int i = 0; i < 4; ++i) {
        int idx = i * 32 + ln;                    // 0..127
        int row = idx >> 4;                       // 0..7
        int kc  = ks * 16 + (idx & 15);
        reg[i] = __ldcg((const float4*)(src + (size_t)(r0 + row) * HH + kc * 4));
    }
}
__device__ __forceinline__ void stage_sts(float* __restrict__ hst,
                                          const float4* reg, int ks, int ln)
{
#pragma unroll
    for (int i = 0; i < 4; ++i) {
        int idx = i * 32 + ln;
        int row = idx >> 4;
        int kc  = ks * 16 + (idx & 15);
        *(float4*)&hst[row * HSTRIDE + kc * 4] = reg[i];
    }
}

// ---------------- persistent scan kernel ----------------
// 128 CTAs x 256 thr, 1/SM. Group g = bid>>4 owns batch rows [g*8, +8).
// cid = bid&15: z cols [cid*32,+32), r cols [512+cid*32,+32), cand cols [cid*32,+32).
// Step: stage h -> r-GEMM(P_rz) -> r reduce + rh out + arrive A
//       -> z-GEMM(P_rz, hides A) -> wait A -> rh LDG (hoisted) -> z reduce
//       -> rh STS -> cand-GEMM(P_c) -> cand reduce + h update + arrive B
//       -> out store -> wait B.
// smem (floats): wg 32x512 z | 32x512 r | wc 32x512 | hst 8x516 | P_rz 2048 | P_c 2048
#define SM_WG   0
#define SM_WC   32768
#define SM_HST  49152
#define SM_PRZ  53280
#define SM_PC   55328
#define SMEM_FLOATS 57376
#define SMEM_BYTES (SMEM_FLOATS * 4)   // 229504 B

__global__ void __launch_bounds__(NTHR, 1) scan_kernel(
    const float* __restrict__ Wg, const float* __restrict__ Wc,
    float* __restrict__ out, int write_outputs, int write_hlast)
{
    extern __shared__ float sm[];
    float* wg   = sm + SM_WG;          // cols 0-31 = z, 32-63 = r
    float* wc   = sm + SM_WC;
    float* hst  = sm + SM_HST;
    float* P_rz = sm + SM_PRZ;
    float* P_c  = sm + SM_PC;

    const int tid = threadIdx.x;
    const int g   = blockIdx.x >> 4;
    const int cid = blockIdx.x & 15;
    const int r0  = g * 8;
    const int c32 = cid * 32;

    // ---- load recurrent weight slabs once (swizzled, k-contiguous per col) ----
    for (int idx = tid; idx < 64 * 512; idx += NTHR) {
        int k = idx >> 6, c = idx & 63;
        int gc = (c < 32) ? (c32 + c) : (512 + c32 + (c - 32));
        float v = Wg[(size_t)(512 + k) * 1024 + gc];
        wg[c * 512 + (((k >> 2) ^ ((c >> 2) & 7)) << 2) + (k & 3)] = v;
    }
    for (int idx = tid; idx < 32 * 512; idx += NTHR) {
        int k = idx >> 5, c = idx & 31;
        float v = Wc[(size_t)(512 + k) * 512 + c32 + c];
        wc[c * 512 + (((k >> 2) ^ ((c >> 2) & 7)) << 2) + (k & 3)] = v;
    }
    __syncthreads();

    const int ks  = tid >> 5;          // 0..7 (k-slice warp)
    const int ln  = tid & 31;
    const int rg2 = ln >> 3, cg2 = ln & 7;

    // this thread's output element (same for r, z, cand); v2 = ks
    const int v2   = ks;
    const int row2 = rg2 * 2 + (v2 >> 2);
    const int col2 = cg2 * 4 + (v2 & 3);
    const int jj2  = c32 + col2;
    const int b2   = r0 + row2;

    unsigned* ctrA = g_ctr + (g * 2) * 32;
    unsigned* ctrB = g_ctr + (g * 2 + 1) * 32;

    // h_prev for this thread's element, carried in a register across steps
    float hprev = __ldcg(g_h + (size_t)b2 * HH + jj2);

    for (int t = 0; t < SEQ; ++t) {
        float4 streg[4];

        // ---- stage h LDGs first (longest-latency), then gx prefetch ----
        stage_ldg(streg, g_h, r0, ks, ln);
        const float* gblk = g_gx + (((size_t)t * 8 + g) * 16 + cid) * 768;
        float gxz = __ldcg(gblk + row2 * 96 + col2);
        float gxr = __ldcg(gblk + row2 * 96 + 32 + col2);
        float gxc = __ldcg(gblk + row2 * 96 + 64 + col2);
        stage_sts(hst, streg, ks, ln);
        __syncwarp();

        // ---- r-GEMM ----
        gemm8(hst, wg + 32 * 512, P_rz, ks, ln, rg2, cg2);
        __syncthreads();

        // ---- r reduce + rh out ----
        {
            float s = 0.f;
#pragma unroll
            for (int q = 0; q < 8; ++q) s += P_rz[(q * 8 + v2) * 32 + ln];
            float r = sigmoidf_(s + gxr);
            __stcg(g_rh + (size_t)b2 * HH + jj2, r * hprev);
        }
        bar_arrive(ctrA);   // syncthreads (frees P_rz for z) + release-add

        // ---- z-GEMM overlaps barrier A propagation ----
        gemm8(hst, wg, P_rz, ks, ln, rg2, cg2);
        __syncthreads();

        bar_wait(ctrA, (unsigned)(t + 1) * 16u);

        // ---- rh stage LDGs hoisted above z reduce (hide L2 latency) ----
        stage_ldg(streg, g_rh, r0, ks, ln);
        float z;
        {
            float s = 0.f;
#pragma unroll
            for (int q = 0; q < 8; ++q) s += P_rz[(q * 8 + v2) * 32 + ln];
            z = sigmoidf_(s + gxz);
        }
        stage_sts(hst, streg, ks, ln);   // own warp's z-GEMM reads are done (program order)
        __syncwarp();

        // ---- cand-GEMM (separate P buffer: no hazard vs z reduce) ----
        gemm8(hst, wc, P_c, ks, ln, rg2, cg2);
        __syncthreads();

        // ---- cand reduce + h update ----
        float hn;
        {
            float s = 0.f;
#pragma unroll
            for (int q = 0; q < 8; ++q) s += P_c[(q * 8 + v2) * 32 + ln];
            float cand = tanhf_(s + gxc);
            hn = fmaf(z, cand - hprev, hprev);   // (1-z)*h + z*cand
            __stcg(g_h + (size_t)b2 * HH + jj2, hn);
        }

        bar_arrive(ctrB);

        // out stores after the release — not on the fence's drain path
        if (write_outputs)
            __stcs(out + ((size_t)t * BB + b2) * HH + jj2, hn);
        if (write_hlast && t == SEQ - 1) {
            size_t off = write_outputs ? (size_t)SEQ * BB * HH : 0;
            out[off + (size_t)b2 * HH + jj2] = hn;
        }
        hprev = hn;                          // carry for next step

        bar_wait(ctrB, (unsigned)(t + 1) * 16u);
    }
}

// ---------------- launch ----------------
extern "C" void kernel_launch(void* const* d_in, const int* in_sizes, int n_in,
                              void* d_out, int out_size) {
    const float* x  = (const float*)d_in[0];
    const float* h0 = (const float*)d_in[1];
    const float* Wg = (const float*)d_in[2];
    const float* bg = (const float*)d_in[3];
    const float* Wc = (const float*)d_in[4];
    const float* bc = (const float*)d_in[5];
    float* out = (float*)d_out;

    cudaFuncSetAttribute(scan_kernel, cudaFuncAttributeMaxDynamicSharedMemorySize,
                         SMEM_BYTES);

    long long full = (long long)SEQ * BB * HH;
    int write_outputs = (out_size >= full) ? 1 : 0;
    long long hlast_off = write_outputs ? full : 0;
    int write_hlast = (out_size >= hlast_off + BB * HH) ? 1 : 0;

    dim3 pgrid(12, 1024);
    precompute_kernel<<<pgrid, NTHR>>>(x, Wg, bg, Wc, bc, h0);
    scan_kernel<<<NCTA, NTHR, SMEM_BYTES>>>(Wg, Wc, out, write_outputs, write_hlast);
}